// round 1
// baseline (speedup 1.0000x reference)
#include <cuda_runtime.h>
#include <math.h>

#define Bdim 64
#define Sdim 1024
#define Idim 1024
#define Hdim 1024
#define NB_REC 128

// Scratch (allocation-free rule: __device__ globals)
__device__ float g_hbuf[2][Bdim * Hdim];
__device__ unsigned g_cnt;
__device__ volatile unsigned g_flag;

// ---------------------------------------------------------------------------
// packed f32x2 FMA (Blackwell): doubles fp32 FMA throughput
// ---------------------------------------------------------------------------
__device__ __forceinline__ void fma2(unsigned long long& c, unsigned long long a,
                                     unsigned long long b) {
    asm("fma.rn.f32x2 %0, %1, %2, %0;" : "+l"(c) : "l"(a), "l"(b));
}
__device__ __forceinline__ float f2sum(unsigned long long v) {
    union { unsigned long long u; float2 f; } x;
    x.u = v;
    return x.f.x + x.f.y;
}

// ---------------------------------------------------------------------------
// barrier state reset (run first every launch -> graph-replay deterministic)
// ---------------------------------------------------------------------------
__global__ void reset_bar() {
    if (threadIdx.x == 0) {
        g_cnt = 0;
        g_flag = 0;
    }
}

__global__ void copy_h(const float* __restrict__ hin) {
    int i = blockIdx.x * blockDim.x + threadIdx.x;
    for (; i < Bdim * Hdim; i += gridDim.x * blockDim.x) g_hbuf[0][i] = hin[i];
}

// ---------------------------------------------------------------------------
// Phase 1: wx = X @ Wih^T + b   (M=65536, N=1024, K=1024), fp32 via f32x2
// CTA tile 128(M) x 64(N), K-chunks of 8. Thread tile 8m x 4n (f32x2 over k).
// ---------------------------------------------------------------------------
__global__ __launch_bounds__(256) void wx_gemm(const float* __restrict__ X,
                                               const float* __restrict__ W,
                                               const float* __restrict__ bias,
                                               float* __restrict__ out) {
    __shared__ float Xs[128 * 8];
    __shared__ float Ws[64 * 10];  // stride 10 -> conflict-free LDS.64 pattern
    const int tid = threadIdx.x;
    const int tn = tid & 15, tm = tid >> 4;
    const long mBase = (long)blockIdx.y * 128;
    const int nBase = blockIdx.x * 64;

    unsigned long long acc[8][4];
#pragma unroll
    for (int i = 0; i < 8; i++)
#pragma unroll
        for (int j = 0; j < 4; j++) acc[i][j] = 0ull;

    const int xrow = tid >> 1, xq = tid & 1;
    const float* Xp = X + (mBase + xrow) * Idim + xq * 4;

    for (int k0 = 0; k0 < Idim; k0 += 8) {
        *reinterpret_cast<float4*>(&Xs[xrow * 8 + xq * 4]) =
            *reinterpret_cast<const float4*>(Xp + k0);
        {
            int r = tid >> 3, c = tid & 7;
            Ws[r * 10 + c] = W[(nBase + r) * Idim + k0 + c];
            int e2 = tid + 256;
            r = e2 >> 3;
            c = e2 & 7;
            Ws[r * 10 + c] = W[(nBase + r) * Idim + k0 + c];
        }
        __syncthreads();
#pragma unroll
        for (int p = 0; p < 4; p++) {
            unsigned long long bfrag[4];
#pragma unroll
            for (int j = 0; j < 4; j++)
                bfrag[j] = *reinterpret_cast<const unsigned long long*>(
                    &Ws[(tn + 16 * j) * 10 + p * 2]);
#pragma unroll
            for (int i = 0; i < 8; i++) {
                unsigned long long a = *reinterpret_cast<const unsigned long long*>(
                    &Xs[(tm * 8 + i) * 8 + p * 2]);
#pragma unroll
                for (int j = 0; j < 4; j++) fma2(acc[i][j], a, bfrag[j]);
            }
        }
        __syncthreads();
    }
#pragma unroll
    for (int j = 0; j < 4; j++) {
        float bv = bias[nBase + tn + 16 * j];
#pragma unroll
        for (int i = 0; i < 8; i++) {
            out[(mBase + tm * 8 + i) * Hdim + nBase + tn + 16 * j] =
                f2sum(acc[i][j]) + bv;
        }
    }
}

// ---------------------------------------------------------------------------
// Phase 2: persistent recurrent kernel.
// grid = 128 CTAs (co-resident). CTA = 16 batches x 32 cols.
// Whh slice (32 cols x 1024) cached in SMEM ONCE for all 1024 steps.
// Per step: stage h slice -> K-split (8 warps) f32x2 partial dots ->
//           smem reduce -> +wx +bias -> tanh -> write y (in place) + h buf ->
//           grid barrier.
// ---------------------------------------------------------------------------
__global__ __launch_bounds__(256, 1) void rnn_recur(const float* __restrict__ Whh,
                                                    const float* __restrict__ bhh,
                                                    float* __restrict__ y,
                                                    float* __restrict__ hlast) {
    extern __shared__ float sm[];
    float* sW = sm;                    // 32 x 1026 (padded: conflict-free LDS.64)
    float* sH = sm + 32 * 1026;        // 16 x 1024
    float* sRed = sH + 16 * 1024;      // 8 x 512

    const int tid = threadIdx.x;
    const int bid = blockIdx.x;
    const int colBase = (bid & 31) * 32;
    const int batchBase = (bid >> 5) * 16;

    // cache Whh slice once
    for (int idx = tid; idx < 32 * 1024; idx += 256) {
        int r = idx >> 10, c = idx & 1023;
        sW[r * 1026 + c] = Whh[(colBase + r) * Hdim + c];
    }

    const int kg = tid >> 5, lane = tid & 31;
    const int c0 = lane & 15, bgrp = lane >> 4;
    const int bOff = bgrp * 8;
    const int kBase = kg * 128;

    for (int s = 0; s < Sdim; s++) {
        const int p = s & 1;
        const float* hsrc = g_hbuf[p];
        // stage h slice (bypass L1: written by other SMs last step)
        for (int it = tid; it < (16 * 1024) / 4; it += 256) {
            int offs = it * 4;
            int b = offs >> 10, k = offs & 1023;
            *reinterpret_cast<float4*>(&sH[offs]) = __ldcg(
                reinterpret_cast<const float4*>(&hsrc[((batchBase + b) << 10) + k]));
        }
        __syncthreads();

        unsigned long long acc[2][8];
#pragma unroll
        for (int j = 0; j < 2; j++)
#pragma unroll
            for (int i = 0; i < 8; i++) acc[j][i] = 0ull;

#pragma unroll 2
        for (int kk = 0; kk < 128; kk += 8) {
            const int k = kBase + kk;
            unsigned long long w[2][4];
#pragma unroll
            for (int j = 0; j < 2; j++) {
                const float* wp = &sW[(c0 + 16 * j) * 1026 + k];
#pragma unroll
                for (int q = 0; q < 4; q++)
                    w[j][q] = *reinterpret_cast<const unsigned long long*>(wp + 2 * q);
            }
#pragma unroll
            for (int i = 0; i < 8; i++) {
                const float* hp = &sH[((bOff + i) << 10) + k];
#pragma unroll
                for (int q = 0; q < 4; q++) {
                    unsigned long long hv =
                        *reinterpret_cast<const unsigned long long*>(hp + 2 * q);
                    fma2(acc[0][i], hv, w[0][q]);
                    fma2(acc[1][i], hv, w[1][q]);
                }
            }
        }
#pragma unroll
        for (int j = 0; j < 2; j++)
#pragma unroll
            for (int i = 0; i < 8; i++)
                sRed[kg * 512 + (bOff + i) * 32 + c0 + 16 * j] = f2sum(acc[j][i]);
        __syncthreads();

        // reduce across 8 K-slices, finish: tanh(wx + hW + b)
        float* hdst = g_hbuf[1 - p];
#pragma unroll
        for (int t = 0; t < 2; t++) {
            int o = tid + t * 256;
            int b = o >> 5, cc = o & 31;
            float sum = 0.f;
#pragma unroll
            for (int g2 = 0; g2 < 8; g2++) sum += sRed[g2 * 512 + o];
            long yi = ((long)(batchBase + b) * Sdim + s) * Hdim + colBase + cc;
            float pre = y[yi] + sum + bhh[colBase + cc];
            float hv = tanhf(pre);
            y[yi] = hv;
            __stcg(&hdst[((batchBase + b) << 10) + colBase + cc], hv);
        }

        // grid barrier (monotonic counter + flag; reset_bar zeroes per launch)
        __syncthreads();
        if (tid == 0) {
            __threadfence();
            unsigned arrived = atomicAdd(&g_cnt, 1u) + 1u;
            unsigned step = (unsigned)(s + 1);
            if (arrived == step * (unsigned)NB_REC) g_flag = step;
            while (g_flag < step) {
            }
            __threadfence();
        }
        __syncthreads();
    }

    // h_last: final h lives in g_hbuf[0] (S even); our slice = our own writes
#pragma unroll
    for (int t = 0; t < 2; t++) {
        int o = tid + t * 256;
        int b = o >> 5, cc = o & 31;
        int hi = ((batchBase + b) << 10) + colBase + cc;
        hlast[hi] = g_hbuf[0][hi];
    }
}

// ---------------------------------------------------------------------------
extern "C" void kernel_launch(void* const* d_in, const int* in_sizes, int n_in,
                              void* d_out, int out_size) {
    const float* x = (const float*)d_in[0];      // [B,S,I]
    const float* h0 = (const float*)d_in[1];     // [B,H]
    const float* Wih_w = (const float*)d_in[2];  // [H,I]
    const float* Wih_b = (const float*)d_in[3];  // [H]
    const float* Whh_w = (const float*)d_in[4];  // [H,H]
    const float* Whh_b = (const float*)d_in[5];  // [H]
    float* y = (float*)d_out;                        // [B,S,H]
    float* hlast = y + (size_t)Bdim * Sdim * Hdim;   // [B,H]

    const int smem_bytes = (32 * 1026 + 16 * 1024 + 8 * 512) * 4;  // 213248
    cudaFuncSetAttribute(rnn_recur, cudaFuncAttributeMaxDynamicSharedMemorySize,
                         smem_bytes);

    reset_bar<<<1, 32>>>();
    copy_h<<<64, 256>>>(h0);
    wx_gemm<<<dim3(Hdim / 64, (Bdim * Sdim) / 128), 256>>>(x, Wih_w, Wih_b, y);
    rnn_recur<<<NB_REC, 256, smem_bytes>>>(Whh_w, Whh_b, y, hlast);
}

// round 4
// speedup vs baseline: 1.2727x; 1.2727x over previous
#include <cuda_runtime.h>
#include <math.h>

#define Bdim 64
#define Sdim 1024
#define Idim 1024
#define Hdim 1024
#define NB_REC 128
#define REC_THREADS 512

// Scratch (allocation-free rule: __device__ globals)
__device__ float g_hbuf[2][Bdim * Hdim];
__device__ unsigned g_cnt;
__device__ volatile unsigned g_flag;

typedef unsigned long long ull;

// ---------------------------------------------------------------------------
// packed f32x2 FMA (Blackwell): 2x fp32 FMA throughput
// ---------------------------------------------------------------------------
__device__ __forceinline__ void fma2(ull& c, ull a, ull b) {
    asm("fma.rn.f32x2 %0, %1, %2, %0;" : "+l"(c) : "l"(a), "l"(b));
}
__device__ __forceinline__ float f2sum(ull v) {
    float2 f = *reinterpret_cast<float2*>(&v);
    return f.x + f.y;
}
__device__ __forceinline__ void cp16(void* d, const void* s) {
    unsigned sd = (unsigned)__cvta_generic_to_shared(d);
    asm volatile("cp.async.cg.shared.global [%0], [%1], 16;" :: "r"(sd), "l"(s));
}
#define CP_COMMIT() asm volatile("cp.async.commit_group;")
#define CP_WAIT(n) asm volatile("cp.async.wait_group %0;" :: "n"(n))

// ---------------------------------------------------------------------------
__global__ void reset_bar() {
    if (threadIdx.x == 0) {
        g_cnt = 0;
        g_flag = 0;
    }
}

__global__ void copy_h(const float* __restrict__ hin) {
    int i = blockIdx.x * blockDim.x + threadIdx.x;
    for (; i < Bdim * Hdim; i += gridDim.x * blockDim.x) g_hbuf[0][i] = hin[i];
}

// ---------------------------------------------------------------------------
// Phase 1: wx = X @ Wih^T + b   (M=65536, N=1024, K=1024)
// CTA tile 128m x 64n, 256 threads, thread tile 8m x 4n (f32x2 along k),
// k-chunk 16, cp.async double-buffered.
// smem rows padded to 20 floats (80B: 16B-aligned, conflict-friendly).
// ---------------------------------------------------------------------------
__global__ __launch_bounds__(256) void wx_gemm(const float* __restrict__ X,
                                               const float* __restrict__ W,
                                               const float* __restrict__ bias,
                                               float* __restrict__ out) {
    __shared__ float As[2][128 * 20];
    __shared__ float Ws[2][64 * 20];
    const int tid = threadIdx.x;
    const int tm = tid >> 4, tn = tid & 15;
    const long mBase = (long)blockIdx.y * 128;
    const int nBase = blockIdx.x * 64;

    const int xr = tid >> 1, xq = (tid & 1) * 8;
    const float* xg = X + (mBase + xr) * Idim + xq;
    const int wr = tid >> 2, wq = (tid & 3) * 4;
    const float* wg = W + (nBase + wr) * Idim + wq;

    ull acc[8][4];
#pragma unroll
    for (int i = 0; i < 8; i++)
#pragma unroll
        for (int j = 0; j < 4; j++) acc[i][j] = 0ull;

    // prologue: tile 0
    cp16(&As[0][xr * 20 + xq], xg);
    cp16(&As[0][xr * 20 + xq + 4], xg + 4);
    cp16(&Ws[0][wr * 20 + wq], wg);
    CP_COMMIT();

    int buf = 0;
    for (int kt = 0; kt < Idim / 16; kt++) {
        if (kt + 1 < Idim / 16) {
            const int k0 = (kt + 1) * 16;
            cp16(&As[buf ^ 1][xr * 20 + xq], xg + k0);
            cp16(&As[buf ^ 1][xr * 20 + xq + 4], xg + k0 + 4);
            cp16(&Ws[buf ^ 1][wr * 20 + wq], wg + k0);
        }
        CP_COMMIT();  // one group per iter (groups retire in commit order)
        CP_WAIT(1);   // current tile's group retired
        __syncthreads();

        const float* A = &As[buf][tm * 8 * 20];
        const float* Bp = &Ws[buf][tn * 20];
#pragma unroll
        for (int q = 0; q < 4; q++) {
            ulonglong2 bt[4];
#pragma unroll
            for (int j = 0; j < 4; j++)
                bt[j] = *reinterpret_cast<const ulonglong2*>(&Bp[j * 320 + q * 4]);
#pragma unroll
            for (int i = 0; i < 8; i++) {
                ulonglong2 at =
                    *reinterpret_cast<const ulonglong2*>(&A[i * 20 + q * 4]);
#pragma unroll
                for (int j = 0; j < 4; j++) fma2(acc[i][j], at.x, bt[j].x);
#pragma unroll
                for (int j = 0; j < 4; j++) fma2(acc[i][j], at.y, bt[j].y);
            }
        }
        __syncthreads();
        buf ^= 1;
    }

#pragma unroll
    for (int j = 0; j < 4; j++) {
        float bv = bias[nBase + tn + 16 * j];
#pragma unroll
        for (int i = 0; i < 8; i++) {
            out[(mBase + tm * 8 + i) * Hdim + nBase + tn + 16 * j] =
                f2sum(acc[i][j]) + bv;
        }
    }
}

// ---------------------------------------------------------------------------
// Phase 2: persistent recurrence. 128 CTAs x 512 threads (1 CTA/SM).
// CTA = 32 cols x 16 batches. Whh slice (32x1024) cached in smem all steps.
// 16 warps = 16 k-groups (k=64 each); thread tile 4 cols x 4 batches.
// Per k-quad: 4 W-LDS.128 + 4 h-LDS.128 -> 32 fma2 (FMA-bound).
// Partial sums via sRed overlay on sH, padded stride-40 rows:
//   slot = wid*640 + b*40 + c  (injective; STS banks 8*bpos+cpos all distinct;
//   LDS reads consecutive) -> conflict-free both directions.
// ---------------------------------------------------------------------------
__global__ __launch_bounds__(REC_THREADS, 1)
void rnn_recur(const float* __restrict__ Whh, const float* __restrict__ bhh,
               float* __restrict__ y, float* __restrict__ hlast) {
    extern __shared__ float sm[];
    float* sW = sm;                  // 32 x 1028
    float* sH = sm + 32 * 1028;      // 16 x 1028
    float* sRed = sH;                // overlay: 16 x 640 (used after sH reads)

    const int tid = threadIdx.x;
    const int bid = blockIdx.x;
    const int colBase = (bid & 31) * 32;
    const int batchBase = (bid >> 5) * 16;

    // cache Whh slice once: 32 rows x 1024 cols = 8192 four-float chunks
#pragma unroll
    for (int i = 0; i < 16; i++) {
        int chunk = tid + i * REC_THREADS;
        int r = chunk >> 8, off = (chunk & 255) * 4;
        *reinterpret_cast<float4*>(&sW[r * 1028 + off]) =
            *reinterpret_cast<const float4*>(&Whh[(colBase + r) * Hdim + off]);
    }

    const int wid = tid >> 5, lane = tid & 31;
    const int cpos = lane & 7;   // col group: cols cpos + 8*ci
    const int bpos = lane >> 3;  // batch group: batches bpos + 4*bi
    const int kBase = wid * 64;

    // finish-stage assignment: one output per thread
    const int ob = tid >> 5;  // batch 0..15
    const int oc = tid & 31;  // col 0..31
    const float bv = bhh[colBase + oc];
    const long ybase = (((long)(batchBase + ob)) << 20) + colBase + oc;
    const int hoff = ((batchBase + ob) << 10) + colBase + oc;
    const int rbase = ob * 40 + oc;  // sRed read base
    float hv = 0.f;

    for (int s = 0; s < Sdim; s++) {
        const int p = s & 1;
        const float* hsrc = g_hbuf[p];
        // stage h slice: 16 rows x 1024 cols = 4096 four-float chunks
#pragma unroll
        for (int i = 0; i < 8; i++) {
            int chunk = tid + i * REC_THREADS;
            int r = chunk >> 8, off = (chunk & 255) * 4;
            cp16(&sH[r * 1028 + off], &hsrc[((batchBase + r) << 10) + off]);
        }
        CP_COMMIT();
        float wxv = __ldg(&y[ybase + ((long)s << 10)]);  // prefetch wx
        CP_WAIT(0);
        __syncthreads();

        ull acc[4][4];
#pragma unroll
        for (int ci = 0; ci < 4; ci++)
#pragma unroll
            for (int bi = 0; bi < 4; bi++) acc[ci][bi] = 0ull;

#pragma unroll 4
        for (int q = 0; q < 16; q++) {
            const int k = kBase + q * 4;
            ulonglong2 wf[4], hf[4];
#pragma unroll
            for (int ci = 0; ci < 4; ci++)
                wf[ci] = *reinterpret_cast<const ulonglong2*>(
                    &sW[(cpos + 8 * ci) * 1028 + k]);
#pragma unroll
            for (int bi = 0; bi < 4; bi++)
                hf[bi] = *reinterpret_cast<const ulonglong2*>(
                    &sH[(bpos + 4 * bi) * 1028 + k]);
#pragma unroll
            for (int ci = 0; ci < 4; ci++)
#pragma unroll
                for (int bi = 0; bi < 4; bi++) fma2(acc[ci][bi], hf[bi].x, wf[ci].x);
#pragma unroll
            for (int ci = 0; ci < 4; ci++)
#pragma unroll
                for (int bi = 0; bi < 4; bi++) fma2(acc[ci][bi], hf[bi].y, wf[ci].y);
        }
        __syncthreads();  // all sH reads done before sRed overlay writes

#pragma unroll
        for (int ci = 0; ci < 4; ci++)
#pragma unroll
            for (int bi = 0; bi < 4; bi++) {
                sRed[wid * 640 + (bpos + 4 * bi) * 40 + cpos + 8 * ci] =
                    f2sum(acc[ci][bi]);
            }
        __syncthreads();

        float sum = 0.f;
#pragma unroll
        for (int w = 0; w < 16; w++) sum += sRed[w * 640 + rbase];

        hv = tanhf(wxv + sum + bv);
        float* hdst = g_hbuf[1 - p];
        __stcg(&hdst[hoff], hv);
        __threadfence();
        __syncthreads();  // whole CTA's h writes fenced before arrive
        if (tid == 0) {
            unsigned arrived = atomicAdd(&g_cnt, 1u) + 1u;
            unsigned step = (unsigned)(s + 1);
            if (arrived == step * (unsigned)NB_REC) g_flag = step;
        }
        y[ybase + ((long)s << 10)] = hv;  // off the barrier critical path
        if (tid == 0) {
            unsigned step = (unsigned)(s + 1);
            while (g_flag < step) {
            }
            __threadfence();  // acquire: other SMs' h writes now visible
        }
        __syncthreads();
    }

    hlast[hoff] = hv;  // final h of this thread's (b,c) slot
}

// ---------------------------------------------------------------------------
extern "C" void kernel_launch(void* const* d_in, const int* in_sizes, int n_in,
                              void* d_out, int out_size) {
    const float* x = (const float*)d_in[0];      // [B,S,I]
    const float* h0 = (const float*)d_in[1];     // [B,H]
    const float* Wih_w = (const float*)d_in[2];  // [H,I]
    const float* Wih_b = (const float*)d_in[3];  // [H]
    const float* Whh_w = (const float*)d_in[4];  // [H,H]
    const float* Whh_b = (const float*)d_in[5];  // [H]
    float* y = (float*)d_out;                       // [B,S,H]
    float* hlast = y + (size_t)Bdim * Sdim * Hdim;  // [B,H]

    const int smem_bytes = (32 + 16) * 1028 * 4;  // 197376
    cudaFuncSetAttribute(rnn_recur, cudaFuncAttributeMaxDynamicSharedMemorySize,
                         smem_bytes);

    reset_bar<<<1, 32>>>();
    copy_h<<<64, 256>>>(h0);
    wx_gemm<<<dim3(Hdim / 64, (Bdim * Sdim) / 128), 256>>>(x, Wih_w, Wih_b, y);
    rnn_recur<<<NB_REC, REC_THREADS, smem_bytes>>>(Whh_w, Whh_b, y, hlast);
}